// round 7
// baseline (speedup 1.0000x reference)
#include <cuda_runtime.h>
#include <cuda_bf16.h>
#include <cstdint>
#include <cstddef>

#define NBATCH 64
#define NTOT   8192
#define THRESH 0.02f
#define KT     64
#define NCH_E  128                 // einsum chunks (K=8192)
#define NCH    176                 // + 48 stim chunks (K=3072)
#define HALF   88                  // chunks per k-slice
#define MTILE  128

// smem per buffer: Ahi 16K | Alo 16K | Bhi 8K | Blo 8K  (SW128, 128B rows)
#define WHI_OFF 0
#define WLO_OFF 16384
#define ZHI_OFF 32768
#define ZLO_OFF 40960
#define BUFB    49152
#define SMEM_TOTAL (2 * BUFB)      // 98304

__device__ float g_gatesum[4];
__device__ float g_accum[NBATCH * NTOT];
__device__ float g_znew[NBATCH * NTOT];

// ---------------- helpers ----------------
static __device__ __forceinline__ uint32_t smem_u32(const void* p) {
    uint32_t a;
    asm("{ .reg .u64 t; cvta.to.shared.u64 t, %1; cvt.u32.u64 %0, t; }" : "=r"(a) : "l"(p));
    return a;
}
#define SWZ(o) ((o) ^ (((o) >> 3) & 0x70))

static __device__ __forceinline__ void ldsm4(uint32_t* r, uint32_t addr) {
    asm volatile("ldmatrix.sync.aligned.m8n8.x4.shared.b16 {%0,%1,%2,%3}, [%4];"
                 : "=r"(r[0]), "=r"(r[1]), "=r"(r[2]), "=r"(r[3]) : "r"(addr));
}
static __device__ __forceinline__ void mma_bf16(float* d, const uint32_t* a,
                                                uint32_t b0, uint32_t b1) {
    asm volatile("mma.sync.aligned.m16n8k16.row.col.f32.bf16.bf16.f32 "
                 "{%0,%1,%2,%3}, {%4,%5,%6,%7}, {%8,%9}, {%0,%1,%2,%3};"
                 : "+f"(d[0]), "+f"(d[1]), "+f"(d[2]), "+f"(d[3])
                 : "r"(a[0]), "r"(a[1]), "r"(a[2]), "r"(a[3]), "r"(b0), "r"(b1));
}

// split (a,b) into packed bf16 hi + lo-residual pairs (lo half of reg = a)
static __device__ __forceinline__ void split2(float a, float b, uint32_t& hp, uint32_t& lp) {
    asm("cvt.rn.bf16x2.f32 %0, %1, %2;" : "=r"(hp) : "f"(b), "f"(a));
    float ha = __uint_as_float(hp << 16);
    float hb = __uint_as_float(hp & 0xffff0000u);
    float la = a - ha;
    float lb = b - hb;
    asm("cvt.rn.bf16x2.f32 %0, %1, %2;" : "=r"(lp) : "f"(lb), "f"(la));
}
// split 8 floats into packed quads
static __device__ __forceinline__ void split8(const float* f, uint4& hp, uint4& lp) {
    uint32_t h[4], l[4];
#pragma unroll
    for (int j = 0; j < 4; j++) split2(f[2 * j], f[2 * j + 1], h[j], l[j]);
    hp = make_uint4(h[0], h[1], h[2], h[3]);
    lp = make_uint4(l[0], l[1], l[2], l[3]);
}

// ---------------- zero + gate ----------------
__global__ void zero_kernel() {
    int idx = blockIdx.x * 256 + threadIdx.x;
    float4* p = (float4*)g_accum;
#pragma unroll
    for (int j = 0; j < 4; j++) p[idx * 4 + j] = make_float4(0.f, 0.f, 0.f, 0.f);
    if (blockIdx.x == 0 && threadIdx.x < 4) g_gatesum[threadIdx.x] = 0.f;
}

__global__ void gate_kernel(const float* __restrict__ Z) {
    int area = blockIdx.x & 3, slice = blockIdx.x >> 2, t = threadIdx.x;
    float s = 0.f;
#pragma unroll
    for (int it = 0; it < 8; it++) {
        int f = t + 256 * it;
        int b = slice * 4 + (f >> 9), a4 = f & 511;
        float4 v = *(const float4*)(Z + (size_t)b * NTOT + (size_t)area * 2048 + a4 * 4);
        s += fabsf(v.x) + fabsf(v.y) + fabsf(v.z) + fabsf(v.w);
    }
#pragma unroll
    for (int o = 16; o; o >>= 1) s += __shfl_xor_sync(0xffffffffu, s, o);
    __shared__ float ws[8];
    if ((t & 31) == 0) ws[t >> 5] = s;
    __syncthreads();
    if (t == 0) {
        float tot = 0.f;
        for (int w = 0; w < 8; w++) tot += ws[w];
        atomicAdd(&g_gatesum[area], tot);
    }
}

// ---------------- main HMMA kernel ----------------
__global__ __launch_bounds__(256, 1)
void main_kernel(const float* __restrict__ x, const float* __restrict__ Z,
                 const float* __restrict__ rw, const float* __restrict__ W,
                 const float* __restrict__ Mk)
{
    extern __shared__ char smem[];
    const uint32_t sb = smem_u32(smem);
    const int t = threadIdx.x, wid = t >> 5, lid = t & 31;
    const int ct = blockIdx.x >> 1;         // M-tile 0..63
    const int ks = blockIdx.x & 1;          // k-slice
    const int n0 = ct * MTILE;
    const int o = ct >> 4;
    const int u0 = (ct & 15) * MTILE;

    float gates[4];
#pragma unroll
    for (int i = 0; i < 4; i++)
        gates[i] = (g_gatesum[i] * (1.0f / 131072.0f) > THRESH) ? 1.f : 0.f;

    // loader indices
    const int ar = t >> 1, ah = t & 1;      // A: row 0..127, k-half
    const int zb = t >> 2, zq = t & 3;      // B: batch 0..63, k-quarter

    float4 wv[8], mv[8], zv[4];
    uint4 apk_h[4], apk_l[4], zpk_h[2], zpk_l[2];

    auto ldg = [&](int c) {
        if (c < NCH_E) {
            int k0 = c * KT, i = k0 >> 11, kl = k0 & 2047;
            const float* wr = W  + ((size_t)(o * 4 + i) * 2048 + u0 + ar) * 2048 + kl + ah * 32;
            const float* mr = Mk + ((size_t)(o * 4 + i) * 2048 + u0 + ar) * 2048 + kl + ah * 32;
#pragma unroll
            for (int j = 0; j < 8; j++) {
                wv[j] = *(const float4*)(wr + j * 4);
                mv[j] = *(const float4*)(mr + j * 4);
            }
            const float* zr = Z + (size_t)zb * NTOT + k0 + zq * 16;
#pragma unroll
            for (int j = 0; j < 4; j++) zv[j] = *(const float4*)(zr + j * 4);
        } else {
            int k0 = (c - NCH_E) * KT;
            const float* wr = rw + (size_t)(n0 + ar) * 3072 + k0 + ah * 32;
#pragma unroll
            for (int j = 0; j < 8; j++) wv[j] = *(const float4*)(wr + j * 4);
            const float* zr = x + (size_t)zb * 3072 + k0 + zq * 16;
#pragma unroll
            for (int j = 0; j < 4; j++) zv[j] = *(const float4*)(zr + j * 4);
        }
    };

    auto cvtA = [&](int g, bool einsum) {
        float f[8];
        float4 a = wv[2 * g], b = wv[2 * g + 1];
        f[0] = a.x; f[1] = a.y; f[2] = a.z; f[3] = a.w;
        f[4] = b.x; f[5] = b.y; f[6] = b.z; f[7] = b.w;
        if (einsum) {
            float4 ma = mv[2 * g], mb = mv[2 * g + 1];
            f[0] *= __saturatef(ma.x); f[1] *= __saturatef(ma.y);
            f[2] *= __saturatef(ma.z); f[3] *= __saturatef(ma.w);
            f[4] *= __saturatef(mb.x); f[5] *= __saturatef(mb.y);
            f[6] *= __saturatef(mb.z); f[7] *= __saturatef(mb.w);
        }
        split8(f, apk_h[g], apk_l[g]);
    };
    auto cvtZ = [&](int g, float zg) {
        float f[8];
        float4 a = zv[2 * g], b = zv[2 * g + 1];
        f[0] = a.x * zg; f[1] = a.y * zg; f[2] = a.z * zg; f[3] = a.w * zg;
        f[4] = b.x * zg; f[5] = b.y * zg; f[6] = b.z * zg; f[7] = b.w * zg;
        split8(f, zpk_h[g], zpk_l[g]);
    };

    auto sts = [&](uint32_t buf) {
#pragma unroll
        for (int g = 0; g < 4; g++) {
            uint32_t sw = SWZ((uint32_t)(ar * 128 + ah * 64 + g * 16));
            asm volatile("st.shared.v4.b32 [%0], {%1,%2,%3,%4};" ::
                         "r"(buf + WHI_OFF + sw),
                         "r"(apk_h[g].x), "r"(apk_h[g].y), "r"(apk_h[g].z), "r"(apk_h[g].w) : "memory");
            asm volatile("st.shared.v4.b32 [%0], {%1,%2,%3,%4};" ::
                         "r"(buf + WLO_OFF + sw),
                         "r"(apk_l[g].x), "r"(apk_l[g].y), "r"(apk_l[g].z), "r"(apk_l[g].w) : "memory");
        }
#pragma unroll
        for (int g = 0; g < 2; g++) {
            uint32_t sw = SWZ((uint32_t)(zb * 128 + zq * 32 + g * 16));
            asm volatile("st.shared.v4.b32 [%0], {%1,%2,%3,%4};" ::
                         "r"(buf + ZHI_OFF + sw),
                         "r"(zpk_h[g].x), "r"(zpk_h[g].y), "r"(zpk_h[g].z), "r"(zpk_h[g].w) : "memory");
            asm volatile("st.shared.v4.b32 [%0], {%1,%2,%3,%4};" ::
                         "r"(buf + ZLO_OFF + sw),
                         "r"(zpk_l[g].x), "r"(zpk_l[g].y), "r"(zpk_l[g].z), "r"(zpk_l[g].w) : "memory");
        }
    };

    // warp tile: mw in 0..3 (32 cols), nw in 0..1 (32 batches)
    const int mw = wid & 3, nw = wid >> 2;
    const int lr = lid & 15, lh = lid >> 4;
    const uint32_t a_row0 = (uint32_t)((mw * 32 + lr) * 128 + lh * 16);
    const uint32_t a_row1 = a_row0 + 16 * 128;
    const uint32_t b_row0 = (uint32_t)((nw * 32 + lr) * 128 + lh * 16);
    const uint32_t b_row1 = b_row0 + 16 * 128;

    float acc[8][4];
#pragma unroll
    for (int i = 0; i < 8; i++)
#pragma unroll
        for (int j = 0; j < 4; j++) acc[i][j] = 0.f;

    // one k-quarter (16 k): hoisted LDSM, then 3 passes of 8 INDEPENDENT MMAs
    auto mma_kk = [&](uint32_t buf, int kk) {
        const uint32_t ko = (uint32_t)(kk * 32);
        uint32_t ah0[4], ah1[4], al0[4], al1[4];
        uint32_t bh0[4], bh1[4], bl0[4], bl1[4];
        ldsm4(ah0, buf + WHI_OFF + SWZ(a_row0 + ko));
        ldsm4(ah1, buf + WHI_OFF + SWZ(a_row1 + ko));
        ldsm4(bh0, buf + ZHI_OFF + SWZ(b_row0 + ko));
        ldsm4(bh1, buf + ZHI_OFF + SWZ(b_row1 + ko));
        ldsm4(al0, buf + WLO_OFF + SWZ(a_row0 + ko));
        ldsm4(al1, buf + WLO_OFF + SWZ(a_row1 + ko));
        ldsm4(bl0, buf + ZLO_OFF + SWZ(b_row0 + ko));
        ldsm4(bl1, buf + ZLO_OFF + SWZ(b_row1 + ko));
        // pass 1: Ah x Bh  (8 independent accumulators)
        mma_bf16(acc[0], ah0, bh0[0], bh0[2]);
        mma_bf16(acc[1], ah0, bh0[1], bh0[3]);
        mma_bf16(acc[2], ah0, bh1[0], bh1[2]);
        mma_bf16(acc[3], ah0, bh1[1], bh1[3]);
        mma_bf16(acc[4], ah1, bh0[0], bh0[2]);
        mma_bf16(acc[5], ah1, bh0[1], bh0[3]);
        mma_bf16(acc[6], ah1, bh1[0], bh1[2]);
        mma_bf16(acc[7], ah1, bh1[1], bh1[3]);
        // pass 2: Ah x Bl
        mma_bf16(acc[0], ah0, bl0[0], bl0[2]);
        mma_bf16(acc[1], ah0, bl0[1], bl0[3]);
        mma_bf16(acc[2], ah0, bl1[0], bl1[2]);
        mma_bf16(acc[3], ah0, bl1[1], bl1[3]);
        mma_bf16(acc[4], ah1, bl0[0], bl0[2]);
        mma_bf16(acc[5], ah1, bl0[1], bl0[3]);
        mma_bf16(acc[6], ah1, bl1[0], bl1[2]);
        mma_bf16(acc[7], ah1, bl1[1], bl1[3]);
        // pass 3: Al x Bh
        mma_bf16(acc[0], al0, bh0[0], bh0[2]);
        mma_bf16(acc[1], al0, bh0[1], bh0[3]);
        mma_bf16(acc[2], al0, bh1[0], bh1[2]);
        mma_bf16(acc[3], al0, bh1[1], bh1[3]);
        mma_bf16(acc[4], al1, bh0[0], bh0[2]);
        mma_bf16(acc[5], al1, bh0[1], bh0[3]);
        mma_bf16(acc[6], al1, bh1[0], bh1[2]);
        mma_bf16(acc[7], al1, bh1[1], bh1[3]);
    };

    const int c0 = ks * HALF, c1 = c0 + HALF;

    // prologue: stage chunk c0
    ldg(c0);
    {
        bool e0 = (c0 < NCH_E);
        float zg0 = e0 ? gates[(c0 * KT) >> 11] : 1.f;
        cvtA(0, e0); cvtA(1, e0); cvtA(2, e0); cvtA(3, e0);
        cvtZ(0, zg0); cvtZ(1, zg0);
        sts(sb);
    }
    __syncthreads();

    for (int c = c0; c < c1; c++) {
        const int p = (c - c0) & 1;
        const uint32_t buf = sb + (uint32_t)p * BUFB;
        const uint32_t nbuf = sb + (uint32_t)(p ^ 1) * BUFB;
        const bool have_next = (c + 1 < c1);
        bool ne = false; float nzg = 1.f;
        if (have_next) {
            ldg(c + 1);                      // issue loads early
            ne = (c + 1 < NCH_E);
            nzg = ne ? gates[((c + 1) * KT) >> 11] : 1.f;
        }
        // kk0/kk1: pure tensor work while next chunk's LDGs are in flight
        mma_kk(buf, 0);
        mma_kk(buf, 1);
        // kk2/kk3: tensor work + conversion of next chunk in the issue gaps
        mma_kk(buf, 2);
        if (have_next) { cvtA(0, ne); cvtA(1, ne); cvtZ(0, nzg); }
        mma_kk(buf, 3);
        if (have_next) { cvtA(2, ne); cvtA(3, ne); cvtZ(1, nzg); sts(nbuf); }
        __syncthreads();
    }

    // epilogue: spread atomics into g_accum
    const int mbase = n0 + mw * 32;
    const int nbase = nw * 32;
    const int r = lid >> 2, cp = (lid & 3) * 2;
#pragma unroll
    for (int mt = 0; mt < 2; mt++) {
#pragma unroll
        for (int nt = 0; nt < 4; nt++) {
            const float* cc = acc[mt * 4 + nt];
            int m = mbase + mt * 16 + r;
            int nb = nbase + nt * 8 + cp;
            atomicAdd(&g_accum[(size_t)nb * NTOT + m],           cc[0]);
            atomicAdd(&g_accum[(size_t)(nb + 1) * NTOT + m],     cc[1]);
            atomicAdd(&g_accum[(size_t)nb * NTOT + m + 8],       cc[2]);
            atomicAdd(&g_accum[(size_t)(nb + 1) * NTOT + m + 8], cc[3]);
        }
    }
}

// ---------------- combine: bias/decay/tanh ----------------
__global__ void combine_kernel(const float* __restrict__ Z, const float* __restrict__ F,
                               const float* __restrict__ rb, const float* __restrict__ bias)
{
    int idx = blockIdx.x * 256 + threadIdx.x;
    int rest = idx & 2047;
    int n4 = rest * 4;
    int o = n4 >> 11;
    float g = (g_gatesum[o] * (1.0f / 131072.0f) > THRESH) ? 1.f : 0.f;
    float4 a  = ((const float4*)g_accum)[idx];
    float4 rv = *(const float4*)(rb + n4);
    float4 bv = *(const float4*)(bias + n4);
    float4 Fv = ((const float4*)F)[idx];
    float4 Zv = ((const float4*)Z)[idx];
    float4 outv;
    outv.x = tanhf(a.x + rv.x + bv.x * g - 0.8f * Fv.x - 0.4f * Zv.x);
    outv.y = tanhf(a.y + rv.y + bv.y * g - 0.8f * Fv.y - 0.4f * Zv.y);
    outv.z = tanhf(a.z + rv.z + bv.z * g - 0.8f * Fv.z - 0.4f * Zv.z);
    outv.w = tanhf(a.w + rv.w + bv.w * g - 0.8f * Fv.w - 0.4f * Zv.w);
    ((float4*)g_znew)[idx] = outv;
}

// ---------------- output projection ----------------
__global__ void out_kernel(const float* __restrict__ out_w, const float* __restrict__ out_b,
                           float* __restrict__ out)
{
    int b = blockIdx.x, t = threadIdx.x;
    float p[11];
#pragma unroll
    for (int j = 0; j < 11; j++) p[j] = 0.f;
    const float4* zr = (const float4*)(g_znew + (size_t)b * NTOT);
#pragma unroll
    for (int it = 0; it < 8; it++) {
        int f4 = t + 256 * it;
        float4 z = zr[f4];
#pragma unroll
        for (int j = 0; j < 11; j++) {
            float4 w = ((const float4*)(out_w + (size_t)j * NTOT))[f4];
            p[j] += z.x * w.x + z.y * w.y + z.z * w.z + z.w * w.w;
        }
    }
    __shared__ float red[11 * 64];
#pragma unroll
    for (int j = 0; j < 11; j++) {
        float v = p[j];
#pragma unroll
        for (int o = 16; o; o >>= 1) v += __shfl_xor_sync(0xffffffffu, v, o);
        if ((t & 31) == 0) red[j * 64 + (t >> 5)] = v;
    }
    __syncthreads();
    if (t < 11) {
        float r = out_b[t];
        for (int w = 0; w < 8; w++) r += red[t * 64 + w];
        out[(size_t)b * 11 + t] = (t < 10) ? r : 1.0f / (1.0f + expf(-r));
    }
}

// ---------------- launch ----------------
extern "C" void kernel_launch(void* const* d_in, const int* in_sizes, int n_in,
                              void* d_out, int out_size) {
    const float* x      = (const float*)d_in[0];
    const float* Z      = (const float*)d_in[1];
    const float* Fstate = (const float*)d_in[2];
    const float* rw     = (const float*)d_in[3];
    const float* rb     = (const float*)d_in[4];
    const float* W      = (const float*)d_in[5];
    const float* Mk     = (const float*)d_in[6];
    const float* bias_d = (const float*)d_in[7];
    const float* out_w  = (const float*)d_in[8];
    const float* out_b  = (const float*)d_in[9];
    float* out = (float*)d_out;

    cudaFuncSetAttribute(main_kernel, cudaFuncAttributeMaxDynamicSharedMemorySize, SMEM_TOTAL);

    zero_kernel<<<128, 256>>>();
    gate_kernel<<<64, 256>>>(Z);
    main_kernel<<<128, 256, SMEM_TOTAL>>>(x, Z, rw, W, Mk);
    combine_kernel<<<512, 256>>>(Z, Fstate, rb, bias_d);
    out_kernel<<<NBATCH, 256>>>(out_w, out_b, out);
}

// round 8
// speedup vs baseline: 1.8841x; 1.8841x over previous
#include <cuda_runtime.h>
#include <cuda_bf16.h>
#include <cstdint>
#include <cstddef>

#define NBATCH 64
#define NTOT   8192
#define THRESH 0.02f
#define KT     64
#define NCH_E  128                 // einsum chunks (K=8192)
#define NCH    176                 // + 48 stim chunks (K=3072)
#define HALF   88                  // chunks per k-slice
#define MTILE  128

// smem per buffer: Ahi 16K | Alo 16K | Bhi 8K | Blo 8K  (SW128, 128B rows)
#define WHI_OFF 0
#define WLO_OFF 16384
#define ZHI_OFF 32768
#define ZLO_OFF 40960
#define BUFB    49152
#define SMEM_TOTAL (2 * BUFB)      // 98304

__device__ float g_gatesum[4];
__device__ float g_accum[NBATCH * NTOT];
__device__ float g_znew[NBATCH * NTOT];

// ---------------- helpers ----------------
static __device__ __forceinline__ uint32_t smem_u32(const void* p) {
    uint32_t a;
    asm("{ .reg .u64 t; cvta.to.shared.u64 t, %1; cvt.u32.u64 %0, t; }" : "=r"(a) : "l"(p));
    return a;
}
#define SWZ(o) ((o) ^ (((o) >> 3) & 0x70))

static __device__ __forceinline__ void ldsm4(uint32_t* r, uint32_t addr) {
    asm volatile("ldmatrix.sync.aligned.m8n8.x4.shared.b16 {%0,%1,%2,%3}, [%4];"
                 : "=r"(r[0]), "=r"(r[1]), "=r"(r[2]), "=r"(r[3]) : "r"(addr));
}
static __device__ __forceinline__ void mma_bf16(float* d, const uint32_t* a,
                                                uint32_t b0, uint32_t b1) {
    asm volatile("mma.sync.aligned.m16n8k16.row.col.f32.bf16.bf16.f32 "
                 "{%0,%1,%2,%3}, {%4,%5,%6,%7}, {%8,%9}, {%0,%1,%2,%3};"
                 : "+f"(d[0]), "+f"(d[1]), "+f"(d[2]), "+f"(d[3])
                 : "r"(a[0]), "r"(a[1]), "r"(a[2]), "r"(a[3]), "r"(b0), "r"(b1));
}

// split (a,b) into packed bf16 hi + lo-residual pair (lo half of reg = a)
static __device__ __forceinline__ void split2(float a, float b, uint32_t& hp, uint32_t& lp) {
    asm("cvt.rn.bf16x2.f32 %0, %1, %2;" : "=r"(hp) : "f"(b), "f"(a));
    float ha = __uint_as_float(hp << 16);
    float hb = __uint_as_float(hp & 0xffff0000u);
    float la = a - ha;
    float lb = b - hb;
    asm("cvt.rn.bf16x2.f32 %0, %1, %2;" : "=r"(lp) : "f"(lb), "f"(la));
}
// split one float4 into hi/lo packed pairs
static __device__ __forceinline__ void split4(float4 f, uint2& h, uint2& l) {
    split2(f.x, f.y, h.x, l.x);
    split2(f.z, f.w, h.y, l.y);
}

// ---------------- zero + gate ----------------
__global__ void zero_kernel() {
    int idx = blockIdx.x * 256 + threadIdx.x;
    float4* p = (float4*)g_accum;
#pragma unroll
    for (int j = 0; j < 4; j++) p[idx * 4 + j] = make_float4(0.f, 0.f, 0.f, 0.f);
    if (blockIdx.x == 0 && threadIdx.x < 4) g_gatesum[threadIdx.x] = 0.f;
}

__global__ void gate_kernel(const float* __restrict__ Z) {
    int area = blockIdx.x & 3, slice = blockIdx.x >> 2, t = threadIdx.x;
    float s = 0.f;
#pragma unroll
    for (int it = 0; it < 8; it++) {
        int f = t + 256 * it;
        int b = slice * 4 + (f >> 9), a4 = f & 511;
        float4 v = *(const float4*)(Z + (size_t)b * NTOT + (size_t)area * 2048 + a4 * 4);
        s += fabsf(v.x) + fabsf(v.y) + fabsf(v.z) + fabsf(v.w);
    }
#pragma unroll
    for (int o = 16; o; o >>= 1) s += __shfl_xor_sync(0xffffffffu, s, o);
    __shared__ float ws[8];
    if ((t & 31) == 0) ws[t >> 5] = s;
    __syncthreads();
    if (t == 0) {
        float tot = 0.f;
        for (int w = 0; w < 8; w++) tot += ws[w];
        atomicAdd(&g_gatesum[area], tot);
    }
}

// ---------------- main HMMA kernel ----------------
__global__ __launch_bounds__(256, 1)
void main_kernel(const float* __restrict__ x, const float* __restrict__ Z,
                 const float* __restrict__ rw, const float* __restrict__ W,
                 const float* __restrict__ Mk)
{
    extern __shared__ char smem[];
    const uint32_t sb = smem_u32(smem);
    const int t = threadIdx.x, wid = t >> 5, lid = t & 31;
    const int ct = blockIdx.x >> 1;         // M-tile 0..63
    const int ks = blockIdx.x & 1;          // k-slice
    const int n0 = ct * MTILE;
    const int o = ct >> 4;
    const int u0 = (ct & 15) * MTILE;

    float gates[4];
#pragma unroll
    for (int i = 0; i < 4; i++)
        gates[i] = (g_gatesum[i] * (1.0f / 131072.0f) > THRESH) ? 1.f : 0.f;

    // COALESCED loader indices: warp lanes contiguous in memory.
    // row slot = v*16 + lr16, k offset = lk*4 floats (16B) -> warp = 2 rows x 256B
    const int lr16 = t >> 4;                // 0..15
    const int lk = t & 15;                  // float4 slot within KT

    float4 wv[8], mv[8], zv[4];
    uint2 ah2[8], al2[8], zh2[4], zl2[4];

    auto ldg = [&](int c) {
        if (c < NCH_E) {
            int k0 = c * KT, i = k0 >> 11, kl = k0 & 2047;
            const size_t base = ((size_t)(o * 4 + i) * 2048 + u0) * 2048 + kl + lk * 4;
#pragma unroll
            for (int v = 0; v < 8; v++) {
                size_t off = base + (size_t)(v * 16 + lr16) * 2048;
                wv[v] = *(const float4*)(W + off);
                mv[v] = *(const float4*)(Mk + off);
            }
#pragma unroll
            for (int v = 0; v < 4; v++)
                zv[v] = *(const float4*)(Z + (size_t)(v * 16 + lr16) * NTOT + k0 + lk * 4);
        } else {
            int k0 = (c - NCH_E) * KT;
#pragma unroll
            for (int v = 0; v < 8; v++)
                wv[v] = *(const float4*)(rw + (size_t)(n0 + v * 16 + lr16) * 3072 + k0 + lk * 4);
#pragma unroll
            for (int v = 0; v < 4; v++)
                zv[v] = *(const float4*)(x + (size_t)(v * 16 + lr16) * 3072 + k0 + lk * 4);
        }
    };

    auto cvtA = [&](int v, bool einsum) {
        float4 f = wv[v];
        if (einsum) {
            float4 m = mv[v];
            f.x *= __saturatef(m.x); f.y *= __saturatef(m.y);
            f.z *= __saturatef(m.z); f.w *= __saturatef(m.w);
        }
        split4(f, ah2[v], al2[v]);
    };
    auto cvtZ = [&](int v, float zg) {
        float4 f = zv[v];
        f.x *= zg; f.y *= zg; f.z *= zg; f.w *= zg;
        split4(f, zh2[v], zl2[v]);
    };

    auto sts = [&](uint32_t buf) {
#pragma unroll
        for (int v = 0; v < 8; v++) {
            uint32_t sw = SWZ((uint32_t)((v * 16 + lr16) * 128 + lk * 8));
            asm volatile("st.shared.v2.b32 [%0], {%1,%2};" ::
                         "r"(buf + WHI_OFF + sw), "r"(ah2[v].x), "r"(ah2[v].y) : "memory");
            asm volatile("st.shared.v2.b32 [%0], {%1,%2};" ::
                         "r"(buf + WLO_OFF + sw), "r"(al2[v].x), "r"(al2[v].y) : "memory");
        }
#pragma unroll
        for (int v = 0; v < 4; v++) {
            uint32_t sw = SWZ((uint32_t)((v * 16 + lr16) * 128 + lk * 8));
            asm volatile("st.shared.v2.b32 [%0], {%1,%2};" ::
                         "r"(buf + ZHI_OFF + sw), "r"(zh2[v].x), "r"(zh2[v].y) : "memory");
            asm volatile("st.shared.v2.b32 [%0], {%1,%2};" ::
                         "r"(buf + ZLO_OFF + sw), "r"(zl2[v].x), "r"(zl2[v].y) : "memory");
        }
    };

    // warp tile: mw in 0..3 (32 cols), nw in 0..1 (32 batches)
    const int mw = wid & 3, nw = wid >> 2;
    const int lr = lid & 15, lh = lid >> 4;
    const uint32_t a_row0 = (uint32_t)((mw * 32 + lr) * 128 + lh * 16);
    const uint32_t a_row1 = a_row0 + 16 * 128;
    const uint32_t b_row0 = (uint32_t)((nw * 32 + lr) * 128 + lh * 16);
    const uint32_t b_row1 = b_row0 + 16 * 128;

    float acc[8][4];
#pragma unroll
    for (int i = 0; i < 8; i++)
#pragma unroll
        for (int j = 0; j < 4; j++) acc[i][j] = 0.f;

    // one k-quarter (16 k): hoisted LDSM, then 3 passes of 8 independent MMAs
    auto mma_kk = [&](uint32_t buf, int kk) {
        const uint32_t ko = (uint32_t)(kk * 32);
        uint32_t ah0[4], ah1[4], al0[4], al1[4];
        uint32_t bh0[4], bh1[4], bl0[4], bl1[4];
        ldsm4(ah0, buf + WHI_OFF + SWZ(a_row0 + ko));
        ldsm4(ah1, buf + WHI_OFF + SWZ(a_row1 + ko));
        ldsm4(bh0, buf + ZHI_OFF + SWZ(b_row0 + ko));
        ldsm4(bh1, buf + ZHI_OFF + SWZ(b_row1 + ko));
        ldsm4(al0, buf + WLO_OFF + SWZ(a_row0 + ko));
        ldsm4(al1, buf + WLO_OFF + SWZ(a_row1 + ko));
        ldsm4(bl0, buf + ZLO_OFF + SWZ(b_row0 + ko));
        ldsm4(bl1, buf + ZLO_OFF + SWZ(b_row1 + ko));
        mma_bf16(acc[0], ah0, bh0[0], bh0[2]);
        mma_bf16(acc[1], ah0, bh0[1], bh0[3]);
        mma_bf16(acc[2], ah0, bh1[0], bh1[2]);
        mma_bf16(acc[3], ah0, bh1[1], bh1[3]);
        mma_bf16(acc[4], ah1, bh0[0], bh0[2]);
        mma_bf16(acc[5], ah1, bh0[1], bh0[3]);
        mma_bf16(acc[6], ah1, bh1[0], bh1[2]);
        mma_bf16(acc[7], ah1, bh1[1], bh1[3]);
        mma_bf16(acc[0], ah0, bl0[0], bl0[2]);
        mma_bf16(acc[1], ah0, bl0[1], bl0[3]);
        mma_bf16(acc[2], ah0, bl1[0], bl1[2]);
        mma_bf16(acc[3], ah0, bl1[1], bl1[3]);
        mma_bf16(acc[4], ah1, bl0[0], bl0[2]);
        mma_bf16(acc[5], ah1, bl0[1], bl0[3]);
        mma_bf16(acc[6], ah1, bl1[0], bl1[2]);
        mma_bf16(acc[7], ah1, bl1[1], bl1[3]);
        mma_bf16(acc[0], al0, bh0[0], bh0[2]);
        mma_bf16(acc[1], al0, bh0[1], bh0[3]);
        mma_bf16(acc[2], al0, bh1[0], bh1[2]);
        mma_bf16(acc[3], al0, bh1[1], bh1[3]);
        mma_bf16(acc[4], al1, bh0[0], bh0[2]);
        mma_bf16(acc[5], al1, bh0[1], bh0[3]);
        mma_bf16(acc[6], al1, bh1[0], bh1[2]);
        mma_bf16(acc[7], al1, bh1[1], bh1[3]);
    };

    const int c0 = ks * HALF, c1 = c0 + HALF;

    // prologue: stage chunk c0
    ldg(c0);
    {
        bool e0 = (c0 < NCH_E);
        float zg0 = e0 ? gates[(c0 * KT) >> 11] : 1.f;
#pragma unroll
        for (int v = 0; v < 8; v++) cvtA(v, e0);
#pragma unroll
        for (int v = 0; v < 4; v++) cvtZ(v, zg0);
        sts(sb);
    }
    __syncthreads();

    for (int c = c0; c < c1; c++) {
        const int p = (c - c0) & 1;
        const uint32_t buf = sb + (uint32_t)p * BUFB;
        const uint32_t nbuf = sb + (uint32_t)(p ^ 1) * BUFB;
        const bool have_next = (c + 1 < c1);
        bool ne = false; float nzg = 1.f;
        if (have_next) {
            ldg(c + 1);                      // issue coalesced loads early
            ne = (c + 1 < NCH_E);
            nzg = ne ? gates[((c + 1) * KT) >> 11] : 1.f;
        }
        mma_kk(buf, 0);
        mma_kk(buf, 1);
        mma_kk(buf, 2);
        if (have_next) {
            cvtA(0, ne); cvtA(1, ne); cvtA(2, ne); cvtA(3, ne);
            cvtZ(0, nzg); cvtZ(1, nzg);
        }
        mma_kk(buf, 3);
        if (have_next) {
            cvtA(4, ne); cvtA(5, ne); cvtA(6, ne); cvtA(7, ne);
            cvtZ(2, nzg); cvtZ(3, nzg);
            sts(nbuf);
        }
        __syncthreads();
    }

    // epilogue: spread atomics into g_accum
    const int mbase = n0 + mw * 32;
    const int nbase = nw * 32;
    const int r = lid >> 2, cp = (lid & 3) * 2;
#pragma unroll
    for (int mt = 0; mt < 2; mt++) {
#pragma unroll
        for (int nt = 0; nt < 4; nt++) {
            const float* cc = acc[mt * 4 + nt];
            int m = mbase + mt * 16 + r;
            int nb = nbase + nt * 8 + cp;
            atomicAdd(&g_accum[(size_t)nb * NTOT + m],           cc[0]);
            atomicAdd(&g_accum[(size_t)(nb + 1) * NTOT + m],     cc[1]);
            atomicAdd(&g_accum[(size_t)nb * NTOT + m + 8],       cc[2]);
            atomicAdd(&g_accum[(size_t)(nb + 1) * NTOT + m + 8], cc[3]);
        }
    }
}

// ---------------- combine: bias/decay/tanh ----------------
__global__ void combine_kernel(const float* __restrict__ Z, const float* __restrict__ F,
                               const float* __restrict__ rb, const float* __restrict__ bias)
{
    int idx = blockIdx.x * 256 + threadIdx.x;
    int rest = idx & 2047;
    int n4 = rest * 4;
    int o = n4 >> 11;
    float g = (g_gatesum[o] * (1.0f / 131072.0f) > THRESH) ? 1.f : 0.f;
    float4 a  = ((const float4*)g_accum)[idx];
    float4 rv = *(const float4*)(rb + n4);
    float4 bv = *(const float4*)(bias + n4);
    float4 Fv = ((const float4*)F)[idx];
    float4 Zv = ((const float4*)Z)[idx];
    float4 outv;
    outv.x = tanhf(a.x + rv.x + bv.x * g - 0.8f * Fv.x - 0.4f * Zv.x);
    outv.y = tanhf(a.y + rv.y + bv.y * g - 0.8f * Fv.y - 0.4f * Zv.y);
    outv.z = tanhf(a.z + rv.z + bv.z * g - 0.8f * Fv.z - 0.4f * Zv.z);
    outv.w = tanhf(a.w + rv.w + bv.w * g - 0.8f * Fv.w - 0.4f * Zv.w);
    ((float4*)g_znew)[idx] = outv;
}

// ---------------- output projection ----------------
__global__ void out_kernel(const float* __restrict__ out_w, const float* __restrict__ out_b,
                           float* __restrict__ out)
{
    int b = blockIdx.x, t = threadIdx.x;
    float p[11];
#pragma unroll
    for (int j = 0; j < 11; j++) p[j] = 0.f;
    const float4* zr = (const float4*)(g_znew + (size_t)b * NTOT);
#pragma unroll
    for (int it = 0; it < 8; it++) {
        int f4 = t + 256 * it;
        float4 z = zr[f4];
#pragma unroll
        for (int j = 0; j < 11; j++) {
            float4 w = ((const float4*)(out_w + (size_t)j * NTOT))[f4];
            p[j] += z.x * w.x + z.y * w.y + z.z * w.z + z.w * w.w;
        }
    }
    __shared__ float red[11 * 64];
#pragma unroll
    for (int j = 0; j < 11; j++) {
        float v = p[j];
#pragma unroll
        for (int o = 16; o; o >>= 1) v += __shfl_xor_sync(0xffffffffu, v, o);
        if ((t & 31) == 0) red[j * 64 + (t >> 5)] = v;
    }
    __syncthreads();
    if (t < 11) {
        float r = out_b[t];
        for (int w = 0; w < 8; w++) r += red[t * 64 + w];
        out[(size_t)b * 11 + t] = (t < 10) ? r : 1.0f / (1.0f + expf(-r));
    }
}

// ---------------- launch ----------------
extern "C" void kernel_launch(void* const* d_in, const int* in_sizes, int n_in,
                              void* d_out, int out_size) {
    const float* x      = (const float*)d_in[0];
    const float* Z      = (const float*)d_in[1];
    const float* Fstate = (const float*)d_in[2];
    const float* rw     = (const float*)d_in[3];
    const float* rb     = (const float*)d_in[4];
    const float* W      = (const float*)d_in[5];
    const float* Mk     = (const float*)d_in[6];
    const float* bias_d = (const float*)d_in[7];
    const float* out_w  = (const float*)d_in[8];
    const float* out_b  = (const float*)d_in[9];
    float* out = (float*)d_out;

    cudaFuncSetAttribute(main_kernel, cudaFuncAttributeMaxDynamicSharedMemorySize, SMEM_TOTAL);

    zero_kernel<<<128, 256>>>();
    gate_kernel<<<64, 256>>>(Z);
    main_kernel<<<128, 256, SMEM_TOTAL>>>(x, Z, rw, W, Mk);
    combine_kernel<<<512, 256>>>(Z, Fstate, rb, bias_d);
    out_kernel<<<NBATCH, 256>>>(out_w, out_b, out);
}